// round 2
// baseline (speedup 1.0000x reference)
#include <cuda_runtime.h>
#include <cstdint>

// ---------------------------------------------------------------------------
// Problem constants
//   fmap1/fmap2: (2, 32, 64, 96) fp32
//   98 "images" (b=2 x 49 displacements), NCHW throughout.
// ---------------------------------------------------------------------------
#define NIMG 98

// Scratch (device globals; allocation-free)
__device__ float g_mvol[NIMG * 64 * 64 * 96];   // 38,535,168
__device__ float g_x1 [NIMG * 96 * 64 * 96];    // 57,802,752
__device__ float g_x2 [NIMG * 128 * 32 * 48];   // 19,267,584
__device__ float g_x3 [NIMG * 128 * 32 * 48];
__device__ float g_x4 [NIMG * 64 * 32 * 48];    //  9,633,792
__device__ float g_x5 [NIMG * 32 * 64 * 96];    // 19,267,584

// ---------------------------------------------------------------------------
// 1) Build correlation volume: image n = ((b*7)+i)*7+j, di=i-3 (x-shift),
//    dj=j-3 (y-shift). ch<32: fmap1 masked; ch>=32: shifted fmap2.
//    valid == in-bounds (sum of 32 random-normal channels is a.s. nonzero).
// ---------------------------------------------------------------------------
__global__ void build_mvol_k(const float* __restrict__ f1,
                             const float* __restrict__ f2) {
  int idx = blockIdx.x * blockDim.x + threadIdx.x;
  if (idx >= NIMG * 64 * 6144) return;
  int x = idx % 96;
  int y = (idx / 96) % 64;
  int c = (idx / 6144) % 64;
  int n = idx / (6144 * 64);
  int b = n / 49, d = n % 49;
  int di = d / 7 - 3;   // x shift
  int dj = d % 7 - 3;   // y shift
  int yy = y + dj, xx = x + di;
  float v = 0.f;
  if (yy >= 0 && yy < 64 && xx >= 0 && xx < 96) {
    if (c < 32) v = f1[((b * 32 + c) * 64 + y) * 96 + x];
    else        v = f2[((b * 32 + (c - 32)) * 64 + yy) * 96 + xx];
  }
  g_mvol[idx] = v;
}

// ---------------------------------------------------------------------------
// 2) 3x3 stride-1 conv, pad 1. Register tiling: thread = 4 px x 4 co.
//    Block = 4 co-groups x 8 rows x (TW/4) col-groups.
//    out[co][y][x] = sum_{ci,ky,kx} w[co][ci][ky][kx] * in[ci][y+ky-1][x+kx-1]
// ---------------------------------------------------------------------------
template <int TW>
__global__ void __launch_bounds__(4 * 8 * (TW / 4))
conv3x3_s1_k(const float* __restrict__ in, const float* __restrict__ w,
             float* __restrict__ out, int Cin, int Cout, int H, int W) {
  constexpr int PXG = TW / 4;
  constexpr int NT  = 4 * 8 * PXG;
  constexpr int RS  = 35;        // smem row stride (conflict-free)
  constexpr int PL  = 10 * RS;   // plane stride per channel

  __shared__ float s_in[8 * PL];                    // 8 ch x 10 x RS
  __shared__ __align__(16) float s_w[8 * 9 * 16];   // [ci][k][co16]

  const int tid = threadIdx.x;
  const int cg  = tid / (8 * PXG);
  const int pid = tid % (8 * PXG);
  const int py  = pid / PXG;
  const int pxg = pid % PXG;

  const int tilesX = W / TW;
  const int tx = blockIdx.x % tilesX;
  const int ty = blockIdx.x / tilesX;
  const int n  = blockIdx.z;
  const int coB = blockIdx.y * 16;
  const int y0 = ty * 8, x0 = tx * TW;

  const float* inN = in + (size_t)n * Cin * H * W;

  float acc[4][4];
#pragma unroll
  for (int q = 0; q < 4; q++)
#pragma unroll
    for (int p = 0; p < 4; p++) acc[q][p] = 0.f;

  for (int cb = 0; cb < Cin; cb += 8) {
    __syncthreads();
    // input tile: 8 ch, rows y0-1..y0+8, cols x0-1..x0+TW
    for (int t = tid; t < 8 * 10 * (TW + 2); t += NT) {
      int c   = t / (10 * (TW + 2));
      int r   = (t / (TW + 2)) % 10;
      int col = t % (TW + 2);
      int gy = y0 - 1 + r, gx = x0 - 1 + col;
      float v = 0.f;
      if (gy >= 0 && gy < H && gx >= 0 && gx < W)
        v = inN[((cb + c) * H + gy) * W + gx];
      s_in[c * PL + r * RS + col] = v;
    }
    // weights: s_w[(lci*9+k)*16 + lco] = w[(coB+lco)*Cin*9 + (cb+lci)*9 + k]
    for (int t = tid; t < 16 * 8 * 9; t += NT) {
      int lco = t & 15;
      int rem = t >> 4;
      int k   = rem % 9;
      int lci = rem / 9;
      s_w[(lci * 9 + k) * 16 + lco] =
          w[((size_t)(coB + lco) * Cin + (cb + lci)) * 9 + k];
    }
    __syncthreads();

#pragma unroll
    for (int ci = 0; ci < 8; ci++) {
#pragma unroll
      for (int ky = 0; ky < 3; ky++) {
        float r[6];
#pragma unroll
        for (int j = 0; j < 6; j++)
          r[j] = s_in[ci * PL + (py + ky) * RS + pxg * 4 + j];
#pragma unroll
        for (int kx = 0; kx < 3; kx++) {
          float4 wv =
              reinterpret_cast<const float4*>(s_w)[(ci * 9 + ky * 3 + kx) * 4 + cg];
#pragma unroll
          for (int p = 0; p < 4; p++) {
            float iv = r[p + kx];
            acc[0][p] += wv.x * iv;
            acc[1][p] += wv.y * iv;
            acc[2][p] += wv.z * iv;
            acc[3][p] += wv.w * iv;
          }
        }
      }
    }
  }

  float* outN = out + (size_t)n * Cout * H * W;
  const int gy = y0 + py;
#pragma unroll
  for (int q = 0; q < 4; q++) {
    int co = coB + cg * 4 + q;
#pragma unroll
    for (int p = 0; p < 4; p++) {
      int gx = x0 + pxg * 4 + p;
      outN[((size_t)co * H + gy) * W + gx] = acc[q][p];
    }
  }
}

// ---------------------------------------------------------------------------
// 3) 3x3 stride-2 conv, pad 1 (64x96 -> 32x48).
// ---------------------------------------------------------------------------
__global__ void __launch_bounds__(128)
conv3x3_s2_k(const float* __restrict__ in, const float* __restrict__ w,
             float* __restrict__ out, int Cin, int Cout) {
  constexpr int IH = 64, IW = 96, OH = 32, OW = 48;
  constexpr int RS = 33;
  constexpr int PL = 17 * RS;

  __shared__ float s_in[8 * PL];                    // 8 ch x 17 x 33
  __shared__ __align__(16) float s_w[8 * 9 * 16];

  const int tid = threadIdx.x;
  const int cg  = tid >> 5;           // warp = co group
  const int py  = (tid & 31) >> 2;    // 0..7
  const int pxg = tid & 3;            // 0..3  (4 px each)

  const int tx = blockIdx.x % 3;      // OW/16 = 3
  const int ty = blockIdx.x / 3;      // OH/8  = 4
  const int n  = blockIdx.z;
  const int coB = blockIdx.y * 16;
  const int y0 = ty * 8, x0 = tx * 16;

  const float* inN = in + (size_t)n * Cin * IH * IW;

  float acc[4][4];
#pragma unroll
  for (int q = 0; q < 4; q++)
#pragma unroll
    for (int p = 0; p < 4; p++) acc[q][p] = 0.f;

  for (int cb = 0; cb < Cin; cb += 8) {
    __syncthreads();
    // input tile rows 2*y0-1 .. 2*y0+15 (17), cols 2*x0-1 .. 2*x0+31 (33)
    for (int t = tid; t < 8 * 17 * 33; t += 128) {
      int c   = t / (17 * 33);
      int r   = (t / 33) % 17;
      int col = t % 33;
      int gy = 2 * y0 - 1 + r, gx = 2 * x0 - 1 + col;
      float v = 0.f;
      if (gy >= 0 && gy < IH && gx >= 0 && gx < IW)
        v = inN[((cb + c) * IH + gy) * IW + gx];
      s_in[c * PL + r * RS + col] = v;
    }
    for (int t = tid; t < 16 * 8 * 9; t += 128) {
      int lco = t & 15;
      int rem = t >> 4;
      int k   = rem % 9;
      int lci = rem / 9;
      s_w[(lci * 9 + k) * 16 + lco] =
          w[((size_t)(coB + lco) * Cin + (cb + lci)) * 9 + k];
    }
    __syncthreads();

#pragma unroll
    for (int ci = 0; ci < 8; ci++) {
#pragma unroll
      for (int ky = 0; ky < 3; ky++) {
        float r[9];
#pragma unroll
        for (int m = 0; m < 9; m++)
          r[m] = s_in[ci * PL + (2 * py + ky) * RS + pxg * 8 + m];
#pragma unroll
        for (int kx = 0; kx < 3; kx++) {
          float4 wv =
              reinterpret_cast<const float4*>(s_w)[(ci * 9 + ky * 3 + kx) * 4 + cg];
#pragma unroll
          for (int p = 0; p < 4; p++) {
            float iv = r[2 * p + kx];
            acc[0][p] += wv.x * iv;
            acc[1][p] += wv.y * iv;
            acc[2][p] += wv.z * iv;
            acc[3][p] += wv.w * iv;
          }
        }
      }
    }
  }

  float* outN = out + (size_t)n * Cout * OH * OW;
  const int gy = y0 + py;
#pragma unroll
  for (int q = 0; q < 4; q++) {
    int co = coB + cg * 4 + q;
#pragma unroll
    for (int p = 0; p < 4; p++) {
      int gx = x0 + pxg * 4 + p;
      outN[((size_t)co * OH + gy) * OW + gx] = acc[q][p];
    }
  }
}

// ---------------------------------------------------------------------------
// 4) Instance norm + leaky ReLU, in place. One block per (n, c).
// ---------------------------------------------------------------------------
__global__ void __launch_bounds__(256)
inorm_leaky_k(float* __restrict__ x, int HW) {
  const size_t base = (size_t)blockIdx.x * HW;
  float s = 0.f, q = 0.f;
  for (int i = threadIdx.x; i < HW; i += 256) {
    float v = x[base + i];
    s += v;
    q += v * v;
  }
#pragma unroll
  for (int o = 16; o > 0; o >>= 1) {
    s += __shfl_xor_sync(0xffffffffu, s, o);
    q += __shfl_xor_sync(0xffffffffu, q, o);
  }
  __shared__ float ss[8], sq[8];
  int wrp = threadIdx.x >> 5, ln = threadIdx.x & 31;
  if (ln == 0) { ss[wrp] = s; sq[wrp] = q; }
  __syncthreads();
  if (threadIdx.x == 0) {
    float S = 0.f, Q = 0.f;
#pragma unroll
    for (int i = 0; i < 8; i++) { S += ss[i]; Q += sq[i]; }
    float m = S / (float)HW;
    float var = Q / (float)HW - m * m;
    ss[0] = m;
    sq[0] = rsqrtf(var + 1e-5f);
  }
  __syncthreads();
  const float m = ss[0], inv = sq[0];
  for (int i = threadIdx.x; i < HW; i += 256) {
    float v = (x[base + i] - m) * inv;
    x[base + i] = v >= 0.f ? v : 0.01f * v;
  }
}

// ---------------------------------------------------------------------------
// 5) 4x4 stride-2 transposed conv (64ch 32x48 -> 32ch 64x96), split into 4
//    output-parity classes; each class is a 2x2-tap conv on the 32x48 grid.
//    out[co][2y+a][2x+b] = sum_{ci,s,t} w5[ci][co][3-(a+2s)][3-(b+2t)]
//                                      * in[ci][y+a+s-1][x+b+t-1]
// ---------------------------------------------------------------------------
__global__ void __launch_bounds__(256)
deconv4x4_k(const float* __restrict__ in, const float* __restrict__ w5,
            float* __restrict__ out) {
  constexpr int IH = 32, IW = 48;
  constexpr int RS = 18, PL = 17 * RS;

  __shared__ float s_in[16 * PL];                 // 16 ch x 17 x 18
  __shared__ __align__(16) float s_w[16 * 4 * 32]; // [ci][tap][co]

  const int parity = blockIdx.y;
  const int a = parity >> 1, b = parity & 1;
  const int n = blockIdx.z;
  const int tx = blockIdx.x % 3;   // subgrid 32x48, tile 16x16 -> 2x3 tiles
  const int ty = blockIdx.x / 3;
  const int tid = threadIdx.x;
  const int ly = tid >> 4, lx = tid & 15;
  const int ybase = ty * 16, xbase = tx * 16;

  const float* inN = in + (size_t)n * 64 * IH * IW;

  float acc[32];
#pragma unroll
  for (int c = 0; c < 32; c++) acc[c] = 0.f;

  for (int cb = 0; cb < 64; cb += 16) {
    __syncthreads();
    // input rows ybase+a-1 .. +16, cols xbase+b-1 .. +16 (17x17, padded)
    for (int t = tid; t < 16 * 17 * 17; t += 256) {
      int c   = t / (17 * 17);
      int r   = (t / 17) % 17;
      int col = t % 17;
      int iy = ybase + a - 1 + r;
      int ix = xbase + b - 1 + col;
      float v = 0.f;
      if (iy >= 0 && iy < IH && ix >= 0 && ix < IW)
        v = inN[((cb + c) * IH + iy) * IW + ix];
      s_in[c * PL + r * RS + col] = v;
    }
    // weights: s_w[lci][s*2+t][co] = w5[(cb+lci)][co][3-(a+2s)][3-(b+2t)]
    for (int t = tid; t < 16 * 4 * 32; t += 256) {
      int co  = t & 31;
      int tap = (t >> 5) & 3;
      int lci = t >> 7;
      int s  = tap >> 1, tt = tap & 1;
      int ky = a + 2 * s, kx = b + 2 * tt;
      s_w[t] = w5[(((size_t)(cb + lci) * 32 + co) * 4 + (3 - ky)) * 4 + (3 - kx)];
    }
    __syncthreads();

#pragma unroll 4
    for (int ci = 0; ci < 16; ci++) {
      float i00 = s_in[ci * PL + (ly + 0) * RS + lx + 0];
      float i01 = s_in[ci * PL + (ly + 0) * RS + lx + 1];
      float i10 = s_in[ci * PL + (ly + 1) * RS + lx + 0];
      float i11 = s_in[ci * PL + (ly + 1) * RS + lx + 1];
      const float4* wp = reinterpret_cast<const float4*>(s_w + ci * 128);
#pragma unroll
      for (int cq = 0; cq < 8; cq++) {
        float4 w0 = wp[cq];       // tap (0,0)
        float4 w1 = wp[8 + cq];   // tap (0,1)
        float4 w2 = wp[16 + cq];  // tap (1,0)
        float4 w3 = wp[24 + cq];  // tap (1,1)
        acc[4 * cq + 0] += w0.x * i00 + w1.x * i01 + w2.x * i10 + w3.x * i11;
        acc[4 * cq + 1] += w0.y * i00 + w1.y * i01 + w2.y * i10 + w3.y * i11;
        acc[4 * cq + 2] += w0.z * i00 + w1.z * i01 + w2.z * i10 + w3.z * i11;
        acc[4 * cq + 3] += w0.w * i00 + w1.w * i01 + w2.w * i10 + w3.w * i11;
      }
    }
  }

  const int oy = 2 * (ybase + ly) + a;
  const int ox = 2 * (xbase + lx) + b;
  float* outN = out + (size_t)n * 32 * 64 * 96;
#pragma unroll
  for (int co = 0; co < 32; co++)
    outN[((size_t)co * 64 + oy) * 96 + ox] = acc[co];
}

// ---------------------------------------------------------------------------
// 6) Final 3x3 conv 32 -> 1 + bias, writes d_out directly.
//    FIX (R1): w6 has 288 elements but blockDim is 256 — load with a strided
//    loop instead of a single guarded load (sw[256..287] were uninitialized).
// ---------------------------------------------------------------------------
__global__ void __launch_bounds__(256)
conv_final_k(const float* __restrict__ in, const float* __restrict__ w6,
             const float* __restrict__ b6, float* __restrict__ out) {
  __shared__ float sw[288];
  __shared__ float sb;
  for (int t = threadIdx.x; t < 288; t += 256) sw[t] = w6[t];
  if (threadIdx.x == 0) sb = b6[0];
  __syncthreads();

  int idx = blockIdx.x * 256 + threadIdx.x;  // 98*6144 = 602112 exact
  int x = idx % 96;
  int y = (idx / 96) % 64;
  int n = idx / 6144;

  const float* inN = in + (size_t)n * 32 * 6144;
  float acc = sb;
#pragma unroll 4
  for (int ci = 0; ci < 32; ci++) {
#pragma unroll
    for (int ky = 0; ky < 3; ky++) {
      int gy = y + ky - 1;
      if (gy < 0 || gy >= 64) continue;
#pragma unroll
      for (int kx = 0; kx < 3; kx++) {
        int gx = x + kx - 1;
        if (gx < 0 || gx >= 96) continue;
        acc += sw[ci * 9 + ky * 3 + kx] * inN[(ci * 64 + gy) * 96 + gx];
      }
    }
  }
  out[idx] = acc;
}

// ---------------------------------------------------------------------------
// Launch
// ---------------------------------------------------------------------------
extern "C" void kernel_launch(void* const* d_in, const int* in_sizes, int n_in,
                              void* d_out, int out_size) {
  const float* f1 = (const float*)d_in[0];
  const float* f2 = (const float*)d_in[1];
  const float* w1 = (const float*)d_in[2];
  const float* w2 = (const float*)d_in[3];
  const float* w3 = (const float*)d_in[4];
  const float* w4 = (const float*)d_in[5];
  const float* w5 = (const float*)d_in[6];
  const float* w6 = (const float*)d_in[7];
  const float* b6 = (const float*)d_in[8];
  float* out = (float*)d_out;

  float *mvol, *x1, *x2, *x3, *x4, *x5;
  cudaGetSymbolAddress((void**)&mvol, g_mvol);
  cudaGetSymbolAddress((void**)&x1, g_x1);
  cudaGetSymbolAddress((void**)&x2, g_x2);
  cudaGetSymbolAddress((void**)&x3, g_x3);
  cudaGetSymbolAddress((void**)&x4, g_x4);
  cudaGetSymbolAddress((void**)&x5, g_x5);

  // 1) correlation volume
  {
    int total = NIMG * 64 * 6144;
    build_mvol_k<<<(total + 255) / 256, 256>>>(f1, f2);
  }

  // 2) conv1: 64 -> 96 on 64x96   (TW=32: tiles 8x3=24, co-groups 6)
  conv3x3_s1_k<32><<<dim3(24, 6, NIMG), 256>>>(mvol, w1, x1, 64, 96, 64, 96);
  inorm_leaky_k<<<NIMG * 96, 256>>>(x1, 6144);

  // 3) conv2 (stride 2): 96 -> 128, 64x96 -> 32x48  (tiles 4x3=12, cog 8)
  conv3x3_s2_k<<<dim3(12, 8, NIMG), 128>>>(x1, w2, x2, 96, 128);
  inorm_leaky_k<<<NIMG * 128, 256>>>(x2, 1536);

  // 4) conv3: 128 -> 128 on 32x48  (TW=16: tiles 4x3=12, cog 8)
  conv3x3_s1_k<16><<<dim3(12, 8, NIMG), 128>>>(x2, w3, x3, 128, 128, 32, 48);
  inorm_leaky_k<<<NIMG * 128, 256>>>(x3, 1536);

  // 5) conv4: 128 -> 64 on 32x48
  conv3x3_s1_k<16><<<dim3(12, 4, NIMG), 128>>>(x3, w4, x4, 128, 64, 32, 48);
  inorm_leaky_k<<<NIMG * 64, 256>>>(x4, 1536);

  // 6) deconv: 64 -> 32, 32x48 -> 64x96 (4 parities x 6 tiles)
  deconv4x4_k<<<dim3(6, 4, NIMG), 256>>>(x4, w5, x5);
  inorm_leaky_k<<<NIMG * 32, 256>>>(x5, 6144);

  // 7) final conv 32 -> 1 + bias
  conv_final_k<<<602112 / 256, 256>>>(x5, w6, b6, out);
}

// round 3
// speedup vs baseline: 1.2788x; 1.2788x over previous
#include <cuda_runtime.h>
#include <cstdint>

// ---------------------------------------------------------------------------
// Padded layouts: every intermediate is [C][H+2][WP] with a 1-px zero halo.
// Borders are NEVER written; __device__ globals are zero-initialized at load,
// so halos stay zero across graph replays -> no bounds checks anywhere.
//   64x96 maps -> HP=66, WP=100 (float4-aligned rows)
//   32x48 maps -> HP=34, WP=52
// ---------------------------------------------------------------------------
#define NIMG 98
#define PL1 (66 * 100)   // 6600 plane for 64x96
#define PL2 (34 * 52)    // 1768 plane for 32x48

__device__ float g_mvol[NIMG * 64 * PL1];   // 41.4M fl
__device__ float g_x1 [NIMG * 96 * PL1];    // 62.1M fl
__device__ float g_x2 [NIMG * 128 * PL2];
__device__ float g_x3 [NIMG * 128 * PL2];
__device__ float g_x4 [NIMG * 64 * PL2];
__device__ float g_x5 [NIMG * 32 * PL1];

// ---------------------------------------------------------------------------
// 1) Correlation volume -> padded mvol. n=(b*7+i)*7+j, di=i-3 (x), dj=j-3 (y)
// ---------------------------------------------------------------------------
__global__ void build_mvol_k(const float* __restrict__ f1,
                             const float* __restrict__ f2) {
  int idx = blockIdx.x * blockDim.x + threadIdx.x;
  if (idx >= NIMG * 64 * 64 * 96) return;
  int x = idx % 96;
  int y = (idx / 96) % 64;
  int c = (idx / 6144) % 64;
  int n = idx / (6144 * 64);
  int b = n / 49, d = n % 49;
  int di = d / 7 - 3;
  int dj = d % 7 - 3;
  int yy = y + dj, xx = x + di;
  float v = 0.f;
  if (yy >= 0 && yy < 64 && xx >= 0 && xx < 96) {
    if (c < 32) v = f1[((b * 32 + c) * 64 + y) * 96 + x];
    else        v = f2[((b * 32 + (c - 32)) * 64 + yy) * 96 + xx];
  }
  g_mvol[((size_t)(n * 64 + c)) * PL1 + (y + 1) * 100 + (x + 1)] = v;
}

// ---------------------------------------------------------------------------
// 2) 3x3 s1 conv on padded tensors. Thread = 4 px x 4 co.
//    Template: TW tile width, H/W logical size, WP padded row stride.
// ---------------------------------------------------------------------------
template <int TW, int H, int W, int WP>
__global__ void __launch_bounds__(8 * TW)
conv3x3_s1_k(const float* __restrict__ in, const float* __restrict__ w,
             float* __restrict__ out, int Cin, int Cout) {
  constexpr int PXG = TW / 4;
  constexpr int NT  = 8 * TW;
  constexpr int RS  = 37;                 // conflict-free odd stride
  constexpr int PLS = 10 * RS;
  constexpr int F4  = (TW + 4) / 4;       // f4 per fill row (9 or 5)
  constexpr int PLANE = (H + 2) * WP;

  __shared__ float s_in[8 * PLS];
  __shared__ __align__(16) float s_w[8 * 9 * 16];

  const int tid = threadIdx.x;
  const int cg  = tid / (8 * PXG);
  const int pid = tid % (8 * PXG);
  const int py  = pid / PXG;
  const int pxg = pid % PXG;

  const int tilesX = W / TW;
  const int tx = blockIdx.x % tilesX;
  const int ty = blockIdx.x / tilesX;
  const int n  = blockIdx.z;
  const int coB = blockIdx.y * 16;
  const int y0 = ty * 8, x0 = tx * TW;

  const float* inN = in + (size_t)n * Cin * PLANE;

  float acc[4][4];
#pragma unroll
  for (int q = 0; q < 4; q++)
#pragma unroll
    for (int p = 0; p < 4; p++) acc[q][p] = 0.f;

  for (int cb = 0; cb < Cin; cb += 8) {
    __syncthreads();
    // fill: 8 ch x 10 rows x F4 float4, no bounds checks (halo is in gmem)
#pragma unroll
    for (int t = tid; t < 8 * 10 * F4; t += NT) {
      int c   = t / (10 * F4);
      int rem = t - c * (10 * F4);
      int r   = rem / F4;
      int q   = rem - r * F4;
      const float4 v = *reinterpret_cast<const float4*>(
          inN + (size_t)(cb + c) * PLANE + (y0 + r) * WP + x0 + 4 * q);
      float* dst = &s_in[c * PLS + r * RS + 4 * q];
      dst[0] = v.x; dst[1] = v.y; dst[2] = v.z; dst[3] = v.w;
    }
    // weights
    for (int t = tid; t < 16 * 8 * 9; t += NT) {
      int lco = t & 15;
      int rem = t >> 4;
      int k   = rem % 9;
      int lci = rem / 9;
      s_w[(lci * 9 + k) * 16 + lco] =
          w[((size_t)(coB + lco) * Cin + (cb + lci)) * 9 + k];
    }
    __syncthreads();

#pragma unroll
    for (int ci = 0; ci < 8; ci++) {
#pragma unroll
      for (int ky = 0; ky < 3; ky++) {
        float r[6];
#pragma unroll
        for (int j = 0; j < 6; j++)
          r[j] = s_in[ci * PLS + (py + ky) * RS + pxg * 4 + j];
#pragma unroll
        for (int kx = 0; kx < 3; kx++) {
          float4 wv =
              reinterpret_cast<const float4*>(s_w)[(ci * 9 + ky * 3 + kx) * 4 + cg];
#pragma unroll
          for (int p = 0; p < 4; p++) {
            float iv = r[p + kx];
            acc[0][p] += wv.x * iv;
            acc[1][p] += wv.y * iv;
            acc[2][p] += wv.z * iv;
            acc[3][p] += wv.w * iv;
          }
        }
      }
    }
  }

  float* outN = out + (size_t)n * Cout * PLANE;
  const int gy = y0 + py + 1;
#pragma unroll
  for (int q = 0; q < 4; q++) {
    int co = coB + cg * 4 + q;
#pragma unroll
    for (int p = 0; p < 4; p++)
      outN[(size_t)co * PLANE + gy * WP + x0 + pxg * 4 + p + 1] = acc[q][p];
  }
}

// ---------------------------------------------------------------------------
// 3) 3x3 s2 conv, padded 66x100 -> padded 34x52.
// ---------------------------------------------------------------------------
__global__ void __launch_bounds__(128)
conv3x3_s2_k(const float* __restrict__ in, const float* __restrict__ w,
             float* __restrict__ out, int Cin, int Cout) {
  constexpr int RS = 37;
  constexpr int PLS = 17 * RS;

  __shared__ float s_in[8 * PLS];     // 8 ch x 17 x 37
  __shared__ __align__(16) float s_w[8 * 9 * 16];

  const int tid = threadIdx.x;
  const int cg  = tid >> 5;
  const int py  = (tid & 31) >> 2;
  const int pxg = tid & 3;

  const int tx = blockIdx.x % 3;
  const int ty = blockIdx.x / 3;
  const int n  = blockIdx.z;
  const int coB = blockIdx.y * 16;
  const int y0 = ty * 8, x0 = tx * 16;

  const float* inN = in + (size_t)n * Cin * PL1;

  float acc[4][4];
#pragma unroll
  for (int q = 0; q < 4; q++)
#pragma unroll
    for (int p = 0; p < 4; p++) acc[q][p] = 0.f;

  for (int cb = 0; cb < Cin; cb += 8) {
    __syncthreads();
    // fill: 8 ch x 17 rows x 9 f4 from padded rows 2y0.., cols 2x0.. (aligned)
#pragma unroll
    for (int c = 0; c < 8; c++) {
      for (int t = tid; t < 17 * 9; t += 128) {
        int r = t / 9;
        int q = t - r * 9;
        const float4 v = *reinterpret_cast<const float4*>(
            inN + (size_t)(cb + c) * PL1 + (2 * y0 + r) * 100 + 2 * x0 + 4 * q);
        float* dst = &s_in[c * PLS + r * RS + 4 * q];
        dst[0] = v.x; dst[1] = v.y; dst[2] = v.z; dst[3] = v.w;
      }
    }
    for (int t = tid; t < 16 * 8 * 9; t += 128) {
      int lco = t & 15;
      int rem = t >> 4;
      int k   = rem % 9;
      int lci = rem / 9;
      s_w[(lci * 9 + k) * 16 + lco] =
          w[((size_t)(coB + lco) * Cin + (cb + lci)) * 9 + k];
    }
    __syncthreads();

#pragma unroll
    for (int ci = 0; ci < 8; ci++) {
#pragma unroll
      for (int ky = 0; ky < 3; ky++) {
        float r[9];
#pragma unroll
        for (int m = 0; m < 9; m++)
          r[m] = s_in[ci * PLS + (2 * py + ky) * RS + pxg * 8 + m];
#pragma unroll
        for (int kx = 0; kx < 3; kx++) {
          float4 wv =
              reinterpret_cast<const float4*>(s_w)[(ci * 9 + ky * 3 + kx) * 4 + cg];
#pragma unroll
          for (int p = 0; p < 4; p++) {
            float iv = r[2 * p + kx];
            acc[0][p] += wv.x * iv;
            acc[1][p] += wv.y * iv;
            acc[2][p] += wv.z * iv;
            acc[3][p] += wv.w * iv;
          }
        }
      }
    }
  }

  float* outN = out + (size_t)n * Cout * PL2;
  const int gy = y0 + py + 1;
#pragma unroll
  for (int q = 0; q < 4; q++) {
    int co = coB + cg * 4 + q;
#pragma unroll
    for (int p = 0; p < 4; p++)
      outN[(size_t)co * PL2 + gy * 52 + x0 + pxg * 4 + p + 1] = acc[q][p];
  }
}

// ---------------------------------------------------------------------------
// 4) Instance norm + leaky, padded in-place. One block per (n,c) plane.
//    Nested constant-stride loops: zero runtime div/mod.
// ---------------------------------------------------------------------------
template <int H, int W, int WP>
__global__ void __launch_bounds__(256)
inorm_leaky_k(float* __restrict__ x) {
  constexpr int PLANE = (H + 2) * WP;
  float* p = x + (size_t)blockIdx.x * PLANE;
  const int wid = threadIdx.x >> 5, ln = threadIdx.x & 31;

  float s = 0.f, q = 0.f;
  for (int y = wid; y < H; y += 8)
    for (int xx = ln; xx < W; xx += 32) {
      float v = p[(y + 1) * WP + xx + 1];
      s += v; q += v * v;
    }
#pragma unroll
  for (int o = 16; o > 0; o >>= 1) {
    s += __shfl_xor_sync(0xffffffffu, s, o);
    q += __shfl_xor_sync(0xffffffffu, q, o);
  }
  __shared__ float ss[8], sq[8];
  if (ln == 0) { ss[wid] = s; sq[wid] = q; }
  __syncthreads();
  if (threadIdx.x == 0) {
    float S = 0.f, Q = 0.f;
#pragma unroll
    for (int i = 0; i < 8; i++) { S += ss[i]; Q += sq[i]; }
    float m = S / (float)(H * W);
    float var = Q / (float)(H * W) - m * m;
    ss[0] = m;
    sq[0] = rsqrtf(var + 1e-5f);
  }
  __syncthreads();
  const float m = ss[0], inv = sq[0];
  for (int y = wid; y < H; y += 8)
    for (int xx = ln; xx < W; xx += 32) {
      float v = (p[(y + 1) * WP + xx + 1] - m) * inv;
      p[(y + 1) * WP + xx + 1] = v >= 0.f ? v : 0.01f * v;
    }
}

// ---------------------------------------------------------------------------
// 5) 4x4 s2 deconv (padded 34x52 in, padded 66x100 out), 4 parity classes.
//    Parity-agnostic 18x20 smem tile (aligned f4 fill).
//    out[co][2y'+a][2x'+b] = sum_{ci,s,t} w5[ci][co][3-(a+2s)][3-(b+2t)]
//                                        * in[ci][y'+a+s-1][x'+b+t-1]
// ---------------------------------------------------------------------------
__global__ void __launch_bounds__(256)
deconv4x4_k(const float* __restrict__ in, const float* __restrict__ w5,
            float* __restrict__ out) {
  constexpr int RS = 20, PLS = 18 * RS;

  __shared__ float s_in[16 * PLS];                  // 16 ch x 18 x 20
  __shared__ __align__(16) float s_w[16 * 4 * 32];  // [ci][tap][co]

  const int parity = blockIdx.y;
  const int a = parity >> 1, b = parity & 1;
  const int n = blockIdx.z;
  const int tx = blockIdx.x % 3;
  const int ty = blockIdx.x / 3;
  const int tid = threadIdx.x;
  const int ly = tid >> 4, lx = tid & 15;
  const int ybase = ty * 16, xbase = tx * 16;

  const float* inN = in + (size_t)n * 64 * PL2;

  float acc[32];
#pragma unroll
  for (int c = 0; c < 32; c++) acc[c] = 0.f;

  for (int cb = 0; cb < 64; cb += 16) {
    __syncthreads();
    // fill: 16 ch x 18 rows x 5 f4, rows ybase.., cols xbase.. (aligned)
#pragma unroll
    for (int t = tid; t < 16 * 18 * 5; t += 256) {
      int c   = t / 90;
      int rem = t - c * 90;
      int r   = rem / 5;
      int q   = rem - r * 5;
      const float4 v = *reinterpret_cast<const float4*>(
          inN + (size_t)(cb + c) * PL2 + (ybase + r) * 52 + xbase + 4 * q);
      float* dst = &s_in[c * PLS + r * RS + 4 * q];
      dst[0] = v.x; dst[1] = v.y; dst[2] = v.z; dst[3] = v.w;
    }
    // weights: s_w[lci][s*2+t][co] = w5[cb+lci][co][3-(a+2s)][3-(b+2t)]
    for (int t = tid; t < 16 * 4 * 32; t += 256) {
      int co  = t & 31;
      int tap = (t >> 5) & 3;
      int lci = t >> 7;
      int s  = tap >> 1, tt = tap & 1;
      s_w[t] = w5[(((size_t)(cb + lci) * 32 + co) * 4 + (3 - (a + 2 * s))) * 4 +
                  (3 - (b + 2 * tt))];
    }
    __syncthreads();

#pragma unroll 4
    for (int ci = 0; ci < 16; ci++) {
      // smem col 0 <-> padded col xbase <-> interior col xbase-1
      float i00 = s_in[ci * PLS + (ly + a + 0) * RS + lx + b + 0];
      float i01 = s_in[ci * PLS + (ly + a + 0) * RS + lx + b + 1];
      float i10 = s_in[ci * PLS + (ly + a + 1) * RS + lx + b + 0];
      float i11 = s_in[ci * PLS + (ly + a + 1) * RS + lx + b + 1];
      const float4* wp = reinterpret_cast<const float4*>(s_w + ci * 128);
#pragma unroll
      for (int cq = 0; cq < 8; cq++) {
        float4 w0 = wp[cq];
        float4 w1 = wp[8 + cq];
        float4 w2 = wp[16 + cq];
        float4 w3 = wp[24 + cq];
        acc[4 * cq + 0] += w0.x * i00 + w1.x * i01 + w2.x * i10 + w3.x * i11;
        acc[4 * cq + 1] += w0.y * i00 + w1.y * i01 + w2.y * i10 + w3.y * i11;
        acc[4 * cq + 2] += w0.z * i00 + w1.z * i01 + w2.z * i10 + w3.z * i11;
        acc[4 * cq + 3] += w0.w * i00 + w1.w * i01 + w2.w * i10 + w3.w * i11;
      }
    }
  }

  const int oy = 2 * (ybase + ly) + a + 1;
  const int ox = 2 * (xbase + lx) + b + 1;
  float* outN = out + (size_t)n * 32 * PL1;
#pragma unroll
  for (int co = 0; co < 32; co++)
    outN[(size_t)co * PL1 + oy * 100 + ox] = acc[co];
}

// ---------------------------------------------------------------------------
// 6) Final 3x3 conv 32 -> 1 + bias: padded x5 -> unpadded d_out.
//    smem-tiled, 8x32 px per block, ci chunks of 8.
// ---------------------------------------------------------------------------
__global__ void __launch_bounds__(256)
conv_final_k(const float* __restrict__ in, const float* __restrict__ w6,
             const float* __restrict__ b6, float* __restrict__ out) {
  constexpr int RS = 37, PLS = 10 * RS;
  __shared__ float s_in[8 * PLS];
  __shared__ float sw[288];
  __shared__ float sb;

  const int tid = threadIdx.x;
  const int tx = blockIdx.x % 3;
  const int ty = blockIdx.x / 3;
  const int n  = blockIdx.y;
  const int y0 = ty * 8, x0 = tx * 32;
  const int px = tid & 31, py = tid >> 5;

  for (int t = tid; t < 288; t += 256) sw[t] = w6[t];
  if (tid == 0) sb = b6[0];

  const float* inN = in + (size_t)n * 32 * PL1;
  float acc = 0.f;

  for (int cb = 0; cb < 32; cb += 8) {
    __syncthreads();
#pragma unroll
    for (int t = tid; t < 8 * 10 * 9; t += 256) {
      int c   = t / 90;
      int rem = t - c * 90;
      int r   = rem / 9;
      int q   = rem - r * 9;
      const float4 v = *reinterpret_cast<const float4*>(
          inN + (size_t)(cb + c) * PL1 + (y0 + r) * 100 + x0 + 4 * q);
      float* dst = &s_in[c * PLS + r * RS + 4 * q];
      dst[0] = v.x; dst[1] = v.y; dst[2] = v.z; dst[3] = v.w;
    }
    __syncthreads();
#pragma unroll
    for (int c = 0; c < 8; c++)
#pragma unroll
      for (int ky = 0; ky < 3; ky++)
#pragma unroll
        for (int kx = 0; kx < 3; kx++)
          acc += sw[(cb + c) * 9 + ky * 3 + kx] *
                 s_in[c * PLS + (py + ky) * RS + px + kx];
  }

  out[(size_t)n * 6144 + (y0 + py) * 96 + x0 + px] = acc + sb;
}

// ---------------------------------------------------------------------------
// Launch
// ---------------------------------------------------------------------------
extern "C" void kernel_launch(void* const* d_in, const int* in_sizes, int n_in,
                              void* d_out, int out_size) {
  const float* f1 = (const float*)d_in[0];
  const float* f2 = (const float*)d_in[1];
  const float* w1 = (const float*)d_in[2];
  const float* w2 = (const float*)d_in[3];
  const float* w3 = (const float*)d_in[4];
  const float* w4 = (const float*)d_in[5];
  const float* w5 = (const float*)d_in[6];
  const float* w6 = (const float*)d_in[7];
  const float* b6 = (const float*)d_in[8];
  float* out = (float*)d_out;

  float *mvol, *x1, *x2, *x3, *x4, *x5;
  cudaGetSymbolAddress((void**)&mvol, g_mvol);
  cudaGetSymbolAddress((void**)&x1, g_x1);
  cudaGetSymbolAddress((void**)&x2, g_x2);
  cudaGetSymbolAddress((void**)&x3, g_x3);
  cudaGetSymbolAddress((void**)&x4, g_x4);
  cudaGetSymbolAddress((void**)&x5, g_x5);

  // 1) correlation volume (padded)
  build_mvol_k<<<(NIMG * 64 * 6144 + 255) / 256, 256>>>(f1, f2);

  // 2) conv1 64->96 @64x96
  conv3x3_s1_k<32, 64, 96, 100><<<dim3(24, 6, NIMG), 256>>>(mvol, w1, x1, 64, 96);
  inorm_leaky_k<64, 96, 100><<<NIMG * 96, 256>>>(x1);

  // 3) conv2 s2 96->128, 64x96 -> 32x48
  conv3x3_s2_k<<<dim3(12, 8, NIMG), 128>>>(x1, w2, x2, 96, 128);
  inorm_leaky_k<32, 48, 52><<<NIMG * 128, 256>>>(x2);

  // 4) conv3 128->128 @32x48
  conv3x3_s1_k<16, 32, 48, 52><<<dim3(12, 8, NIMG), 128>>>(x2, w3, x3, 128, 128);
  inorm_leaky_k<32, 48, 52><<<NIMG * 128, 256>>>(x3);

  // 5) conv4 128->64 @32x48
  conv3x3_s1_k<16, 32, 48, 52><<<dim3(12, 4, NIMG), 128>>>(x3, w4, x4, 128, 64);
  inorm_leaky_k<32, 48, 52><<<NIMG * 64, 256>>>(x4);

  // 6) deconv 64->32, 32x48 -> 64x96
  deconv4x4_k<<<dim3(6, 4, NIMG), 256>>>(x4, w5, x5);
  inorm_leaky_k<64, 96, 100><<<NIMG * 32, 256>>>(x5);

  // 7) final conv 32->1 + bias
  conv_final_k<<<dim3(24, NIMG), 256>>>(x5, w6, b6, out);
}